// round 2
// baseline (speedup 1.0000x reference)
#include <cuda_runtime.h>
#include <math.h>

#define TT 256
#define BB 64
#define DD 1024
#define ND (3*DD)        // 3072
#define MTOT (TT*BB)     // 16384

// ---------------- scratch ----------------
__device__ float g_xproj[(size_t)MTOT * ND];   // [T*B, 3D] input projections
__device__ float g_heff[2][BB * DD];           // ping-pong effective hidden state
__device__ unsigned g_count;
__device__ unsigned g_release;
__device__ int g_dflag;                        // 0=i32, 1=u8, 2=f32 dones encoding

// ---------------- helpers ----------------
__device__ __forceinline__ unsigned f2tf(float x) {
    unsigned y;
    asm("cvt.rna.tf32.f32 %0, %1;" : "=r"(y) : "f"(x));
    return y;
}
__device__ __forceinline__ float f2tf_f(float x) { return __uint_as_float(f2tf(x)); }
__device__ __forceinline__ unsigned fu(float x) { return __float_as_uint(x); }

__device__ __forceinline__ void mma_tf32(float c[4], const unsigned a[4], const unsigned b[2]) {
    asm volatile(
        "mma.sync.aligned.m16n8k8.row.col.f32.tf32.tf32.f32 "
        "{%0,%1,%2,%3}, {%4,%5,%6,%7}, {%8,%9}, {%0,%1,%2,%3};\n"
        : "+f"(c[0]), "+f"(c[1]), "+f"(c[2]), "+f"(c[3])
        : "r"(a[0]), "r"(a[1]), "r"(a[2]), "r"(a[3]),
          "r"(b[0]), "r"(b[1]));
}

__device__ __forceinline__ bool get_done(const void* p, int idx, int flag) {
    if (flag == 1) return ((const unsigned char*)p)[idx] != 0;
    if (flag == 0) return ((const int*)p)[idx] != 0;
    return ((const float*)p)[idx] != 0.0f;
}

__device__ __forceinline__ float sigmoidf_(float x) {
    return 1.0f / (1.0f + __expf(-x));
}

// ---------------- reset + dones-dtype detection ----------------
__global__ void reset_and_detect(const void* dones_raw) {
    __shared__ int bad_f32, bad_i32;
    int tid = threadIdx.x;
    if (tid == 0) { g_count = 0u; g_release = 0u; bad_f32 = 0; bad_i32 = 0; }
    __syncthreads();
    const float* pf = (const float*)dones_raw;
    const int*   pi = (const int*)dones_raw;
    int n32 = (TT * BB) / 4;  // only first T*B bytes: safe for smallest (u8) buffer
    int lf = 0, li = 0;
    for (int i = tid; i < n32; i += blockDim.x) {
        float v = pf[i];
        if (!(v == 0.0f || v == 1.0f)) lf = 1;
        int w = pi[i];
        if (!(w == 0 || w == 1)) li = 1;
    }
    if (lf) atomicOr(&bad_f32, 1);
    if (li) atomicOr(&bad_i32, 1);
    __syncthreads();
    if (tid == 0) {
        int flag;
        if (!bad_f32) flag = 2;        // exactly 0.0f/1.0f everywhere -> float32
        else if (!bad_i32) flag = 0;   // int 0/1 -> int32
        else flag = 1;                 // byte stream 0/1 -> uint8 (numpy bool)
        g_dflag = flag;
    }
}

// ---------------- kernel A: x_proj = ins @ W_i + b_i ----------------
// C[16384,3072] = A[16384,1024] * B[1024,3072]; TF32 mma, 128x128 CTA tiles.
#define AK 32
__global__ __launch_bounds__(256) void xproj_kernel(
    const float* __restrict__ ins, const float* __restrict__ Wi,
    const float* __restrict__ bi)
{
    __shared__ float As[128][AK + 1];
    __shared__ float Bs[AK][128 + 4];

    int tid  = threadIdx.x;
    int mBase = blockIdx.y * 128;
    int nBase = blockIdx.x * 128;

    int warp = tid >> 5, lane = tid & 31;
    int wm = warp >> 2, wn = warp & 3;      // warp tile: rows wm*64.., cols wn*32..
    int g = lane >> 2, tg = lane & 3;

    float acc[4][4][4];
#pragma unroll
    for (int mt = 0; mt < 4; mt++)
#pragma unroll
        for (int nt = 0; nt < 4; nt++)
#pragma unroll
            for (int i = 0; i < 4; i++) acc[mt][nt][i] = 0.0f;

    for (int kb = 0; kb < DD; kb += AK) {
        // stage A: 128 x 32  (FIX: loop over 4 row-blocks; 256 thr x 4 x float4 = 4096)
        {
            int r = tid >> 3;           // 0..31
            int c = (tid & 7) << 2;     // 0,4,...,28
#pragma unroll
            for (int p = 0; p < 4; p++) {
                int rr = r + p * 32;
                float4 v = *(const float4*)&ins[(size_t)(mBase + rr) * DD + kb + c];
                As[rr][c + 0] = f2tf_f(v.x);
                As[rr][c + 1] = f2tf_f(v.y);
                As[rr][c + 2] = f2tf_f(v.z);
                As[rr][c + 3] = f2tf_f(v.w);
            }
        }
        // stage B: 32 x 128
        {
            int r = tid >> 5;           // 0..7
            int c = (tid & 31) << 2;
#pragma unroll
            for (int p = 0; p < 4; p++) {
                int rr = r + p * 8;
                float4 v = *(const float4*)&Wi[(size_t)(kb + rr) * ND + nBase + c];
                Bs[rr][c + 0] = f2tf_f(v.x);
                Bs[rr][c + 1] = f2tf_f(v.y);
                Bs[rr][c + 2] = f2tf_f(v.z);
                Bs[rr][c + 3] = f2tf_f(v.w);
            }
        }
        __syncthreads();

#pragma unroll
        for (int kk = 0; kk < AK; kk += 8) {
            unsigned a[4][4];
#pragma unroll
            for (int mt = 0; mt < 4; mt++) {
                int r0 = wm * 64 + mt * 16;
                a[mt][0] = fu(As[r0 + g][kk + tg]);
                a[mt][1] = fu(As[r0 + 8 + g][kk + tg]);
                a[mt][2] = fu(As[r0 + g][kk + 4 + tg]);
                a[mt][3] = fu(As[r0 + 8 + g][kk + 4 + tg]);
            }
            unsigned b[4][2];
#pragma unroll
            for (int nt = 0; nt < 4; nt++) {
                int c0 = wn * 32 + nt * 8;
                b[nt][0] = fu(Bs[kk + tg][c0 + g]);
                b[nt][1] = fu(Bs[kk + 4 + tg][c0 + g]);
            }
#pragma unroll
            for (int mt = 0; mt < 4; mt++)
#pragma unroll
                for (int nt = 0; nt < 4; nt++)
                    mma_tf32(acc[mt][nt], a[mt], b[nt]);
        }
        __syncthreads();
    }

    // epilogue: add bias, store
#pragma unroll
    for (int mt = 0; mt < 4; mt++) {
#pragma unroll
        for (int nt = 0; nt < 4; nt++) {
            int col = nBase + wn * 32 + nt * 8 + 2 * tg;
            float b0 = bi[col], b1 = bi[col + 1];
            int r0 = mBase + wm * 64 + mt * 16 + g;
            float2 v0 = make_float2(acc[mt][nt][0] + b0, acc[mt][nt][1] + b1);
            float2 v1 = make_float2(acc[mt][nt][2] + b0, acc[mt][nt][3] + b1);
            *(float2*)&g_xproj[(size_t)r0 * ND + col] = v0;
            *(float2*)&g_xproj[(size_t)(r0 + 8) * ND + col] = v1;
        }
    }
}

// ---------------- kernel R: persistent GRU recurrence ----------------
#define RG  64     // persistent CTAs (all co-resident on 148+ SMs)
#define RKC 64
#define FPC 16     // features per CTA (RG*FPC == DD)

__device__ __forceinline__ void grid_barrier(unsigned expected) {
    __syncthreads();
    if (threadIdx.x == 0) {
        __threadfence();
        unsigned prev = atomicAdd(&g_count, 1u);
        if (prev + 1u == expected) {
            atomicExch(&g_release, expected);
        } else {
            while (atomicAdd(&g_release, 0u) < expected) { __nanosleep(64); }
        }
        __threadfence();
    }
    __syncthreads();
}

__global__ __launch_bounds__(256) void gru_kernel(
    const float* __restrict__ hiddens, const void* __restrict__ dones,
    const float* __restrict__ init_carry, const float* __restrict__ Wh,
    const float* __restrict__ bhn, float* __restrict__ out)
{
    __shared__ float Hs[BB][RKC + 1];     // h_eff tile (tf32-rounded)
    __shared__ float Ws[RKC][48 + 1];     // W_h columns tile
    __shared__ float Ps[BB][48 + 2];      // GEMM result

    int tid = threadIdx.x;
    int f0 = blockIdx.x * FPC;
    int dflag = g_dflag;

    int warp = tid >> 5, lane = tid & 31;
    int wm = warp & 3, wn = warp >> 2;    // wm: m-tile (16 rows), wn: n-half (24 cols)
    int g = lane >> 2, tg = lane & 3;

    // ---- prologue: h_eff[0] = done[0] ? hiddens[0] : init_carry (own features)
#pragma unroll
    for (int ii = 0; ii < 4; ii++) {
        int e = tid + ii * 256;           // 0..1023
        int b = e >> 4, j = e & 15;
        int f = f0 + j;
        bool dn = get_done(dones, 0 * BB + b, dflag);
        float v = dn ? hiddens[(size_t)b * DD + f] : init_carry[(size_t)b * DD + f];
        g_heff[0][b * DD + f] = v;
    }
    unsigned bar_no = 1;
    grid_barrier(RG * bar_no); bar_no++;

    for (int t = 0; t < TT; t++) {
        int cur = t & 1, nxt = cur ^ 1;
        const float* hsrc = g_heff[cur];

        float acc[3][4];
#pragma unroll
        for (int nt = 0; nt < 3; nt++)
#pragma unroll
            for (int i = 0; i < 4; i++) acc[nt][i] = 0.0f;

        for (int kb = 0; kb < DD; kb += RKC) {
            // stage Hs: 64 x 64
            {
                int r = tid >> 4;
                int c = (tid & 15) << 2;
#pragma unroll
                for (int p = 0; p < 4; p++) {
                    int rr = r + p * 16;
                    float4 v = *(const float4*)&hsrc[rr * DD + kb + c];
                    Hs[rr][c + 0] = f2tf_f(v.x);
                    Hs[rr][c + 1] = f2tf_f(v.y);
                    Hs[rr][c + 2] = f2tf_f(v.z);
                    Hs[rr][c + 3] = f2tf_f(v.w);
                }
            }
            // stage Ws: 64 x 48  (cols: [r|z|n] x 16 features)
            for (int e = tid; e < RKC * 48; e += 256) {
                int k = e / 48, c = e % 48;
                int gate = c >> 4, j = c & 15;
                Ws[k][c] = f2tf_f(Wh[(size_t)(kb + k) * ND + gate * DD + f0 + j]);
            }
            __syncthreads();

#pragma unroll
            for (int kk = 0; kk < RKC; kk += 8) {
                unsigned a[4];
                int r0 = wm * 16;
                a[0] = fu(Hs[r0 + g][kk + tg]);
                a[1] = fu(Hs[r0 + 8 + g][kk + tg]);
                a[2] = fu(Hs[r0 + g][kk + 4 + tg]);
                a[3] = fu(Hs[r0 + 8 + g][kk + 4 + tg]);
#pragma unroll
                for (int nt = 0; nt < 3; nt++) {
                    unsigned bfrag[2];
                    int c0 = wn * 24 + nt * 8;
                    bfrag[0] = fu(Ws[kk + tg][c0 + g]);
                    bfrag[1] = fu(Ws[kk + 4 + tg][c0 + g]);
                    mma_tf32(acc[nt], a, bfrag);
                }
            }
            __syncthreads();
        }

        // write GEMM result to smem
#pragma unroll
        for (int nt = 0; nt < 3; nt++) {
            int r0 = wm * 16 + g;
            int c0 = wn * 24 + nt * 8 + 2 * tg;
            Ps[r0][c0]     = acc[nt][0];
            Ps[r0][c0 + 1] = acc[nt][1];
            Ps[r0 + 8][c0]     = acc[nt][2];
            Ps[r0 + 8][c0 + 1] = acc[nt][3];
        }
        __syncthreads();

        // gates + update for own 16 features
#pragma unroll
        for (int ii = 0; ii < 4; ii++) {
            int e = tid + ii * 256;
            int b = e >> 4, j = e & 15;
            int f = f0 + j;
            const float* xb = &g_xproj[((size_t)t * BB + b) * ND];
            float xr = xb[f], xz = xb[DD + f], xn = xb[2 * DD + f];
            float r = sigmoidf_(xr + Ps[b][j]);
            float z = sigmoidf_(xz + Ps[b][16 + j]);
            float n = tanhf(xn + r * (Ps[b][32 + j] + bhn[f]));
            float he = hsrc[b * DD + f];
            float hnew = (1.0f - z) * n + z * he;
            out[BB * DD + ((size_t)t * BB + b) * DD + f] = hnew;  // ys
            if (t == TT - 1) {
                out[(size_t)b * DD + f] = hnew;                    // final_carry
            } else {
                bool dn = get_done(dones, (t + 1) * BB + b, dflag);
                float nv = dn ? hiddens[((size_t)(t + 1) * BB + b) * DD + f] : hnew;
                g_heff[nxt][b * DD + f] = nv;
            }
        }

        grid_barrier(RG * bar_no); bar_no++;
    }
}

// ---------------- launch ----------------
extern "C" void kernel_launch(void* const* d_in, const int* in_sizes, int n_in,
                              void* d_out, int out_size) {
    const float* ins        = (const float*)d_in[0];
    const float* hiddens    = (const float*)d_in[1];
    const void*  dones      = (const void*)d_in[2];
    const float* init_carry = (const float*)d_in[3];
    const float* Wi         = (const float*)d_in[4];
    const float* Wh         = (const float*)d_in[5];
    const float* bi         = (const float*)d_in[6];
    const float* bhn        = (const float*)d_in[7];
    float* out = (float*)d_out;

    reset_and_detect<<<1, 256>>>(dones);

    dim3 gA(ND / 128, MTOT / 128);   // (24, 128)
    xproj_kernel<<<gA, 256>>>(ins, Wi, bi);

    gru_kernel<<<RG, 256>>>(hiddens, dones, init_carry, Wh, bhn, out);
}

// round 3
// speedup vs baseline: 2.8702x; 2.8702x over previous
#include <cuda_runtime.h>
#include <math.h>

#define TT 256
#define BB 64
#define DD 1024
#define ND (3*DD)        // 3072
#define MTOT (TT*BB)     // 16384

// ---------------- scratch ----------------
__device__ float g_xproj[(size_t)MTOT * ND];   // [T*B, 3D] input projections
__device__ float g_heff[2][BB * DD];           // ping-pong effective hidden state
__device__ unsigned g_count;
__device__ unsigned g_release;

// ---------------- helpers ----------------
__device__ __forceinline__ unsigned f2tf(float x) {
    unsigned y;
    asm("cvt.rna.tf32.f32 %0, %1;" : "=r"(y) : "f"(x));
    return y;
}
__device__ __forceinline__ float f2tf_f(float x) { return __uint_as_float(f2tf(x)); }
__device__ __forceinline__ unsigned fu(float x) { return __float_as_uint(x); }

__device__ __forceinline__ void mma_tf32(float c[4], const unsigned a[4], const unsigned b[2]) {
    asm volatile(
        "mma.sync.aligned.m16n8k8.row.col.f32.tf32.tf32.f32 "
        "{%0,%1,%2,%3}, {%4,%5,%6,%7}, {%8,%9}, {%0,%1,%2,%3};\n"
        : "+f"(c[0]), "+f"(c[1]), "+f"(c[2]), "+f"(c[3])
        : "r"(a[0]), "r"(a[1]), "r"(a[2]), "r"(a[3]),
          "r"(b[0]), "r"(b[1]));
}

__device__ __forceinline__ bool get_done(const void* p, int idx, int flag) {
    if (flag == 1) return ((const unsigned char*)p)[idx] != 0;
    if (flag == 0) return ((const int*)p)[idx] != 0;
    return ((const float*)p)[idx] != 0.0f;
}

__device__ __forceinline__ float sigmoidf_(float x) {
    return 1.0f / (1.0f + __expf(-x));
}

// ---------------- reset barrier words ----------------
__global__ void reset_kernel() {
    g_count = 0u;
    g_release = 0u;
}

// ---------------- kernel A: x_proj = ins @ W_i + b_i ----------------
// C[16384,3072] = A[16384,1024] * B[1024,3072]; TF32 mma, 128x128 CTA tiles.
#define AK 32
#define AS_S 36      // 36 mod 32 == 4 -> a-fragment banks = 4g+tg (conflict-free)
#define BS_S 132     // 132 mod 32 == 4 -> b-fragment banks = 4tg+g (conflict-free)
__global__ __launch_bounds__(256) void xproj_kernel(
    const float* __restrict__ ins, const float* __restrict__ Wi,
    const float* __restrict__ bi)
{
    __shared__ float As[128 * AS_S];
    __shared__ float Bs[AK * BS_S];

    int tid  = threadIdx.x;
    int mBase = blockIdx.y * 128;
    int nBase = blockIdx.x * 128;

    int warp = tid >> 5, lane = tid & 31;
    int wm = warp >> 2, wn = warp & 3;
    int g = lane >> 2, tg = lane & 3;

    float acc[4][4][4];
#pragma unroll
    for (int mt = 0; mt < 4; mt++)
#pragma unroll
        for (int nt = 0; nt < 4; nt++)
#pragma unroll
            for (int i = 0; i < 4; i++) acc[mt][nt][i] = 0.0f;

    int ra = tid >> 3;              // 0..31
    int ca = (tid & 7) << 2;        // 0..28
    int rb = tid >> 5;              // 0..7
    int cb = (tid & 31) << 2;

    float4 av[4], bv[4];
    // preload kb = 0
#pragma unroll
    for (int p = 0; p < 4; p++)
        av[p] = *(const float4*)&ins[(size_t)(mBase + ra + p * 32) * DD + ca];
#pragma unroll
    for (int p = 0; p < 4; p++)
        bv[p] = *(const float4*)&Wi[(size_t)(rb + p * 8) * ND + nBase + cb];

    for (int kb = 0; kb < DD; kb += AK) {
        // commit staged regs to smem (tf32-rounded)
#pragma unroll
        for (int p = 0; p < 4; p++) {
            float* d = &As[(ra + p * 32) * AS_S + ca];
            d[0] = f2tf_f(av[p].x); d[1] = f2tf_f(av[p].y);
            d[2] = f2tf_f(av[p].z); d[3] = f2tf_f(av[p].w);
        }
#pragma unroll
        for (int p = 0; p < 4; p++) {
            float* d = &Bs[(rb + p * 8) * BS_S + cb];
            d[0] = f2tf_f(bv[p].x); d[1] = f2tf_f(bv[p].y);
            d[2] = f2tf_f(bv[p].z); d[3] = f2tf_f(bv[p].w);
        }
        __syncthreads();

        // prefetch next k-block while computing
        if (kb + AK < DD) {
#pragma unroll
            for (int p = 0; p < 4; p++)
                av[p] = *(const float4*)&ins[(size_t)(mBase + ra + p * 32) * DD + kb + AK + ca];
#pragma unroll
            for (int p = 0; p < 4; p++)
                bv[p] = *(const float4*)&Wi[(size_t)(kb + AK + rb + p * 8) * ND + nBase + cb];
        }

#pragma unroll
        for (int kk = 0; kk < AK; kk += 8) {
            unsigned a[4][4];
#pragma unroll
            for (int mt = 0; mt < 4; mt++) {
                int r0 = wm * 64 + mt * 16;
                a[mt][0] = fu(As[(r0 + g) * AS_S + kk + tg]);
                a[mt][1] = fu(As[(r0 + 8 + g) * AS_S + kk + tg]);
                a[mt][2] = fu(As[(r0 + g) * AS_S + kk + 4 + tg]);
                a[mt][3] = fu(As[(r0 + 8 + g) * AS_S + kk + 4 + tg]);
            }
            unsigned b[4][2];
#pragma unroll
            for (int nt = 0; nt < 4; nt++) {
                int c0 = wn * 32 + nt * 8;
                b[nt][0] = fu(Bs[(kk + tg) * BS_S + c0 + g]);
                b[nt][1] = fu(Bs[(kk + 4 + tg) * BS_S + c0 + g]);
            }
#pragma unroll
            for (int mt = 0; mt < 4; mt++)
#pragma unroll
                for (int nt = 0; nt < 4; nt++)
                    mma_tf32(acc[mt][nt], a[mt], b[nt]);
        }
        __syncthreads();
    }

    // epilogue: add bias, store
#pragma unroll
    for (int mt = 0; mt < 4; mt++) {
#pragma unroll
        for (int nt = 0; nt < 4; nt++) {
            int col = nBase + wn * 32 + nt * 8 + 2 * tg;
            float b0 = bi[col], b1 = bi[col + 1];
            int r0 = mBase + wm * 64 + mt * 16 + g;
            float2 v0 = make_float2(acc[mt][nt][0] + b0, acc[mt][nt][1] + b1);
            float2 v1 = make_float2(acc[mt][nt][2] + b0, acc[mt][nt][3] + b1);
            *(float2*)&g_xproj[(size_t)r0 * ND + col] = v0;
            *(float2*)&g_xproj[(size_t)(r0 + 8) * ND + col] = v1;
        }
    }
}

// ---------------- kernel R: persistent GRU recurrence ----------------
#define RG  64     // persistent CTAs
#define RKC 64     // k chunk
#define FPC 16     // features per CTA (RG*FPC == DD)
#define HS_S 68    // 68 mod 32 == 4 -> a-fragment banks conflict-free
#define WT_S 1028  // 1028 mod 32 == 4 -> b-fragment banks conflict-free
#define PS_S 50

// dyn smem layout: ws[48*1028] | hs[64*68] (Ps unioned into hs)
#define SMEM_WS 0
#define SMEM_HS (48 * WT_S)
#define GRU_SMEM_BYTES ((48 * WT_S + BB * HS_S) * 4)

__device__ __forceinline__ void grid_barrier(unsigned expected) {
    __syncthreads();
    if (threadIdx.x == 0) {
        __threadfence();
        unsigned prev = atomicAdd(&g_count, 1u);
        if (prev + 1u == expected) {
            atomicExch(&g_release, expected);
        } else {
            const volatile unsigned* rp = (const volatile unsigned*)&g_release;
            while (*rp < expected) { __nanosleep(32); }
        }
        __threadfence();
    }
    __syncthreads();
}

__global__ __launch_bounds__(256) void gru_kernel(
    const float* __restrict__ hiddens, const void* __restrict__ dones,
    const float* __restrict__ init_carry, const float* __restrict__ Wh,
    const float* __restrict__ bhn, float* __restrict__ out)
{
    extern __shared__ float sm[];
    float* ws = &sm[SMEM_WS];   // [48][1028]  W_h slice, transposed, tf32
    float* hs = &sm[SMEM_HS];   // [64][68]    h tile
    float* ps = &sm[SMEM_HS];   // [64][50]    GEMM result (union with hs)

    int tid = threadIdx.x;
    int f0 = blockIdx.x * FPC;

    int warp = tid >> 5, lane = tid & 31;
    int wm = warp & 3, wn = warp >> 2;
    int g = lane >> 2, tg = lane & 3;

    // ---- local dones-dtype detection (first 256 words / 1024 u8 entries)
    int dflag;
    {
        int lf = 0, li = 0;
        const float* pf = (const float*)dones;
        const int*   pi = (const int*)dones;
        for (int i = lane; i < 256; i += 32) {
            float v = pf[i];
            if (!(v == 0.0f || v == 1.0f)) lf = 1;
            int w = pi[i];
            if (!(w == 0 || w == 1)) li = 1;
        }
        lf = __any_sync(0xffffffffu, lf);
        li = __any_sync(0xffffffffu, li);
        dflag = (!lf) ? 2 : ((!li) ? 0 : 1);
    }

    // ---- one-time: load W_h slice transposed into smem (tf32)
    // ws[c][k] = Wh[k*ND + gate*DD + f0 + j],  c = gate*16 + j
    for (int k0 = warp; k0 < DD; k0 += 8) {
        int gate = lane >> 4;          // 0,1
        int j = lane & 15;
        float v0 = Wh[(size_t)k0 * ND + gate * DD + f0 + j];
        ws[(gate * 16 + j) * WT_S + k0] = f2tf_f(v0);
        if (lane < 16) {
            float v1 = Wh[(size_t)k0 * ND + 2 * DD + f0 + lane];
            ws[(32 + lane) * WT_S + k0] = f2tf_f(v1);
        }
    }

    // ---- prologue: h_eff[0] = done[0] ? hiddens[0] : init_carry (own features)
#pragma unroll
    for (int ii = 0; ii < 4; ii++) {
        int e = tid + ii * 256;
        int b = e >> 4, j = e & 15;
        int f = f0 + j;
        bool dn = get_done(dones, b, dflag);
        float v = dn ? hiddens[(size_t)b * DD + f] : init_carry[(size_t)b * DD + f];
        g_heff[0][b * DD + f] = v;
    }
    __syncthreads();   // ws visible to all warps
    unsigned bar_no = 1;
    grid_barrier(RG * bar_no); bar_no++;

    int rh = tid >> 4;              // 0..15
    int ch = (tid & 15) << 2;       // 0..60

    for (int t = 0; t < TT; t++) {
        int cur = t & 1, nxt = cur ^ 1;
        const float* hsrc = g_heff[cur];

        float acc[3][4];
#pragma unroll
        for (int nt = 0; nt < 3; nt++)
#pragma unroll
            for (int i = 0; i < 4; i++) acc[nt][i] = 0.0f;

        float4 pv[4];
#pragma unroll
        for (int p = 0; p < 4; p++)
            pv[p] = *(const float4*)&hsrc[(rh + p * 16) * DD + ch];

        for (int kb = 0; kb < DD; kb += RKC) {
            // commit staged h regs
#pragma unroll
            for (int p = 0; p < 4; p++) {
                float* d = &hs[(rh + p * 16) * HS_S + ch];
                d[0] = f2tf_f(pv[p].x); d[1] = f2tf_f(pv[p].y);
                d[2] = f2tf_f(pv[p].z); d[3] = f2tf_f(pv[p].w);
            }
            __syncthreads();
            // prefetch next chunk
            if (kb + RKC < DD) {
#pragma unroll
                for (int p = 0; p < 4; p++)
                    pv[p] = *(const float4*)&hsrc[(rh + p * 16) * DD + kb + RKC + ch];
            }

#pragma unroll
            for (int kk = 0; kk < RKC; kk += 8) {
                unsigned a[4];
                int r0 = wm * 16;
                a[0] = fu(hs[(r0 + g) * HS_S + kk + tg]);
                a[1] = fu(hs[(r0 + 8 + g) * HS_S + kk + tg]);
                a[2] = fu(hs[(r0 + g) * HS_S + kk + 4 + tg]);
                a[3] = fu(hs[(r0 + 8 + g) * HS_S + kk + 4 + tg]);
#pragma unroll
                for (int nt = 0; nt < 3; nt++) {
                    int c0 = wn * 24 + nt * 8;
                    unsigned bfrag[2];
                    bfrag[0] = fu(ws[(c0 + g) * WT_S + kb + kk + tg]);
                    bfrag[1] = fu(ws[(c0 + g) * WT_S + kb + kk + 4 + tg]);
                    mma_tf32(acc[nt], a, bfrag);
                }
            }
            __syncthreads();
        }

        // write GEMM result into ps (unioned with hs; hs dead now)
#pragma unroll
        for (int nt = 0; nt < 3; nt++) {
            int r0 = wm * 16 + g;
            int c0 = wn * 24 + nt * 8 + 2 * tg;
            ps[r0 * PS_S + c0]       = acc[nt][0];
            ps[r0 * PS_S + c0 + 1]   = acc[nt][1];
            ps[(r0 + 8) * PS_S + c0]     = acc[nt][2];
            ps[(r0 + 8) * PS_S + c0 + 1] = acc[nt][3];
        }
        __syncthreads();

        // gates + update for own 16 features
#pragma unroll
        for (int ii = 0; ii < 4; ii++) {
            int e = tid + ii * 256;
            int b = e >> 4, j = e & 15;
            int f = f0 + j;
            const float* xb = &g_xproj[((size_t)t * BB + b) * ND];
            float xr = xb[f], xz = xb[DD + f], xn = xb[2 * DD + f];
            float r = sigmoidf_(xr + ps[b * PS_S + j]);
            float z = sigmoidf_(xz + ps[b * PS_S + 16 + j]);
            float n = tanhf(xn + r * (ps[b * PS_S + 32 + j] + bhn[f]));
            float he = hsrc[b * DD + f];
            float hnew = (1.0f - z) * n + z * he;
            out[BB * DD + ((size_t)t * BB + b) * DD + f] = hnew;  // ys
            if (t == TT - 1) {
                out[(size_t)b * DD + f] = hnew;                    // final_carry
            } else {
                bool dn = get_done(dones, (t + 1) * BB + b, dflag);
                float nv = dn ? hiddens[((size_t)(t + 1) * BB + b) * DD + f] : hnew;
                g_heff[nxt][b * DD + f] = nv;
            }
        }

        grid_barrier(RG * bar_no); bar_no++;
    }
}

// ---------------- launch ----------------
extern "C" void kernel_launch(void* const* d_in, const int* in_sizes, int n_in,
                              void* d_out, int out_size) {
    const float* ins        = (const float*)d_in[0];
    const float* hiddens    = (const float*)d_in[1];
    const void*  dones      = (const void*)d_in[2];
    const float* init_carry = (const float*)d_in[3];
    const float* Wi         = (const float*)d_in[4];
    const float* Wh         = (const float*)d_in[5];
    const float* bi         = (const float*)d_in[6];
    const float* bhn        = (const float*)d_in[7];
    float* out = (float*)d_out;

    static int smem_set = 0;
    if (!smem_set) {
        cudaFuncSetAttribute(gru_kernel,
            cudaFuncAttributeMaxDynamicSharedMemorySize, GRU_SMEM_BYTES);
        smem_set = 1;
    }

    reset_kernel<<<1, 1>>>();

    dim3 gA(ND / 128, MTOT / 128);   // (24, 128)
    xproj_kernel<<<gA, 256>>>(ins, Wi, bi);

    gru_kernel<<<RG, 256, GRU_SMEM_BYTES>>>(hiddens, dones, init_carry, Wh, bhn, out);
}

// round 4
// speedup vs baseline: 4.3262x; 1.5073x over previous
#include <cuda_runtime.h>
#include <math.h>

#define TT 256
#define BB 64
#define DD 1024
#define ND (3*DD)        // 3072
#define MTOT (TT*BB)     // 16384

#define RG 64            // GRU CTAs
#define HELPERS 84       // xproj helper CTAs
#define GRID_ALL (RG + HELPERS)   // 148 = one full wave
#define NTILE_N (ND / 128)        // 24
#define NTILE_M (MTOT / 128)      // 128

// ---------------- scratch ----------------
__device__ float g_xproj[(size_t)MTOT * ND];   // [T*B, 3D]
__device__ float g_heff[2][BB * DD];           // ping-pong effective hidden
__device__ unsigned g_count;
__device__ unsigned g_release;
__device__ unsigned g_tilecnt[NTILE_M];        // per-mblock xproj completion (24 each)

// ---------------- helpers ----------------
__device__ __forceinline__ unsigned f2tf(float x) {
    unsigned y;
    asm("cvt.rna.tf32.f32 %0, %1;" : "=r"(y) : "f"(x));
    return y;
}
__device__ __forceinline__ float f2tf_f(float x) { return __uint_as_float(f2tf(x)); }
__device__ __forceinline__ unsigned fu(float x) { return __float_as_uint(x); }

__device__ __forceinline__ void mma_tf32(float c[4], const unsigned a[4], const unsigned b[2]) {
    asm volatile(
        "mma.sync.aligned.m16n8k8.row.col.f32.tf32.tf32.f32 "
        "{%0,%1,%2,%3}, {%4,%5,%6,%7}, {%8,%9}, {%0,%1,%2,%3};\n"
        : "+f"(c[0]), "+f"(c[1]), "+f"(c[2]), "+f"(c[3])
        : "r"(a[0]), "r"(a[1]), "r"(a[2]), "r"(a[3]),
          "r"(b[0]), "r"(b[1]));
}

__device__ __forceinline__ bool get_done(const void* p, int idx, int flag) {
    if (flag == 1) return ((const unsigned char*)p)[idx] != 0;
    if (flag == 0) return ((const int*)p)[idx] != 0;
    return ((const float*)p)[idx] != 0.0f;
}

__device__ __forceinline__ float sigmoidf_(float x) {
    return 1.0f / (1.0f + __expf(-x));
}

// ---------------- reset ----------------
__global__ void reset_kernel() {
    int t = threadIdx.x;
    if (t == 0) { g_count = 0u; g_release = 0u; }
    if (t < NTILE_M) g_tilecnt[t] = 0u;
}

// ---------------- geometry ----------------
#define AK 32
#define AS_S 36      // mod 32 == 4 -> conflict-free a-frags
#define BS_S 132     // mod 32 == 4 -> conflict-free b-frags
#define RKC 64
#define FPC 16
#define HS_S 68      // mod 32 == 4
#define WT_S 1028    // mod 32 == 4
#define PS_S 50

// gru dyn smem: ws[48*1028] | hsA[64*68] | hsB[64*68];  ps unions into hsA
#define SMEM_WS 0
#define SMEM_HSA (48 * WT_S)
#define SMEM_HSB (48 * WT_S + BB * HS_S)
#define GRU_SMEM_BYTES ((48 * WT_S + 2 * BB * HS_S) * 4)   // 232,192 B

__device__ __forceinline__ void grid_barrier(unsigned expected) {
    __syncthreads();
    if (threadIdx.x == 0) {
        __threadfence();
        unsigned prev = atomicAdd(&g_count, 1u);
        if (prev + 1u == expected) {
            atomicExch(&g_release, expected);
        } else {
            const volatile unsigned* rp = (const volatile unsigned*)&g_release;
            while (*rp < expected) { __nanosleep(20); }
        }
        __threadfence();
    }
    __syncthreads();
}

// ---------------- helper path: xproj tiles ----------------
__device__ void helper_xproj(float* sm, const float* __restrict__ ins,
                             const float* __restrict__ Wi,
                             const float* __restrict__ bi, int hid)
{
    float* As = sm;                    // 128*36
    float* Bs = sm + 128 * AS_S;       // 32*132

    int tid  = threadIdx.x;
    int warp = tid >> 5, lane = tid & 31;
    int wm = warp >> 2, wn = warp & 3;
    int g = lane >> 2, tg = lane & 3;
    int ra = tid >> 3;
    int ca = (tid & 7) << 2;
    int rb = tid >> 5;
    int cb = (tid & 31) << 2;

    for (int tile = hid; tile < NTILE_M * NTILE_N; tile += HELPERS) {
        int mb = tile / NTILE_N, nb = tile % NTILE_N;
        int mBase = mb * 128, nBase = nb * 128;

        float acc[4][4][4];
#pragma unroll
        for (int mt = 0; mt < 4; mt++)
#pragma unroll
            for (int nt = 0; nt < 4; nt++)
#pragma unroll
                for (int i = 0; i < 4; i++) acc[mt][nt][i] = 0.0f;

        float4 av[4], bv[4];
#pragma unroll
        for (int p = 0; p < 4; p++)
            av[p] = *(const float4*)&ins[(size_t)(mBase + ra + p * 32) * DD + ca];
#pragma unroll
        for (int p = 0; p < 4; p++)
            bv[p] = *(const float4*)&Wi[(size_t)(rb + p * 8) * ND + nBase + cb];

        for (int kb = 0; kb < DD; kb += AK) {
#pragma unroll
            for (int p = 0; p < 4; p++) {
                float* d = &As[(ra + p * 32) * AS_S + ca];
                d[0] = f2tf_f(av[p].x); d[1] = f2tf_f(av[p].y);
                d[2] = f2tf_f(av[p].z); d[3] = f2tf_f(av[p].w);
            }
#pragma unroll
            for (int p = 0; p < 4; p++) {
                float* d = &Bs[(rb + p * 8) * BS_S + cb];
                d[0] = f2tf_f(bv[p].x); d[1] = f2tf_f(bv[p].y);
                d[2] = f2tf_f(bv[p].z); d[3] = f2tf_f(bv[p].w);
            }
            __syncthreads();

            if (kb + AK < DD) {
#pragma unroll
                for (int p = 0; p < 4; p++)
                    av[p] = *(const float4*)&ins[(size_t)(mBase + ra + p * 32) * DD + kb + AK + ca];
#pragma unroll
                for (int p = 0; p < 4; p++)
                    bv[p] = *(const float4*)&Wi[(size_t)(kb + AK + rb + p * 8) * ND + nBase + cb];
            }

#pragma unroll
            for (int kk = 0; kk < AK; kk += 8) {
                unsigned a[4][4];
#pragma unroll
                for (int mt = 0; mt < 4; mt++) {
                    int r0 = wm * 64 + mt * 16;
                    a[mt][0] = fu(As[(r0 + g) * AS_S + kk + tg]);
                    a[mt][1] = fu(As[(r0 + 8 + g) * AS_S + kk + tg]);
                    a[mt][2] = fu(As[(r0 + g) * AS_S + kk + 4 + tg]);
                    a[mt][3] = fu(As[(r0 + 8 + g) * AS_S + kk + 4 + tg]);
                }
                unsigned b[4][2];
#pragma unroll
                for (int nt = 0; nt < 4; nt++) {
                    int c0 = wn * 32 + nt * 8;
                    b[nt][0] = fu(Bs[(kk + tg) * BS_S + c0 + g]);
                    b[nt][1] = fu(Bs[(kk + 4 + tg) * BS_S + c0 + g]);
                }
#pragma unroll
                for (int mt = 0; mt < 4; mt++)
#pragma unroll
                    for (int nt = 0; nt < 4; nt++)
                        mma_tf32(acc[mt][nt], a[mt], b[nt]);
            }
            __syncthreads();
        }

        // epilogue: bias + store
#pragma unroll
        for (int mt = 0; mt < 4; mt++) {
#pragma unroll
            for (int nt = 0; nt < 4; nt++) {
                int col = nBase + wn * 32 + nt * 8 + 2 * tg;
                float b0 = bi[col], b1 = bi[col + 1];
                int r0 = mBase + wm * 64 + mt * 16 + g;
                float2 v0 = make_float2(acc[mt][nt][0] + b0, acc[mt][nt][1] + b1);
                float2 v1 = make_float2(acc[mt][nt][2] + b0, acc[mt][nt][3] + b1);
                *(float2*)&g_xproj[(size_t)r0 * ND + col] = v0;
                *(float2*)&g_xproj[(size_t)(r0 + 8) * ND + col] = v1;
            }
        }
        __threadfence();
        __syncthreads();
        if (tid == 0) atomicAdd(&g_tilecnt[mb], 1u);
    }
}

// ---------------- fused persistent kernel ----------------
__global__ __launch_bounds__(256) void fused_kernel(
    const float* __restrict__ ins, const float* __restrict__ hiddens,
    const void* __restrict__ dones, const float* __restrict__ init_carry,
    const float* __restrict__ Wi, const float* __restrict__ Wh,
    const float* __restrict__ bi, const float* __restrict__ bhn,
    float* __restrict__ out)
{
    extern __shared__ float sm[];
    int bid = blockIdx.x;
    if (bid >= RG) { helper_xproj(sm, ins, Wi, bi, bid - RG); return; }

    float* ws  = &sm[SMEM_WS];    // [48][1028]
    float* hsA = &sm[SMEM_HSA];   // [64][68]
    float* hsB = &sm[SMEM_HSB];   // [64][68]
    float* ps  = &sm[SMEM_HSA];   // [64][50] union with hsA

    int tid = threadIdx.x;
    int f0 = bid * FPC;

    int warp = tid >> 5, lane = tid & 31;
    int wm = warp & 3, wn = warp >> 2;
    int g = lane >> 2, tg = lane & 3;

    // dones-dtype detection (prefix only; valid for smallest u8 layout)
    int dflag;
    {
        int lf = 0, li = 0;
        const float* pf = (const float*)dones;
        const int*   pi = (const int*)dones;
        for (int i = lane; i < 256; i += 32) {
            float v = pf[i];
            if (!(v == 0.0f || v == 1.0f)) lf = 1;
            int w = pi[i];
            if (!(w == 0 || w == 1)) li = 1;
        }
        lf = __any_sync(0xffffffffu, lf);
        li = __any_sync(0xffffffffu, li);
        dflag = (!lf) ? 2 : ((!li) ? 0 : 1);
    }

    // one-time: W_h slice transposed into smem (tf32)
    for (int k0 = warp; k0 < DD; k0 += 8) {
        int gate = lane >> 4;
        int j = lane & 15;
        float v0 = Wh[(size_t)k0 * ND + gate * DD + f0 + j];
        ws[(gate * 16 + j) * WT_S + k0] = f2tf_f(v0);
        if (lane < 16) {
            float v1 = Wh[(size_t)k0 * ND + 2 * DD + f0 + lane];
            ws[(32 + lane) * WT_S + k0] = f2tf_f(v1);
        }
    }

    // per-thread hoisted bhn
    float bh[4];
#pragma unroll
    for (int ii = 0; ii < 4; ii++) bh[ii] = bhn[f0 + ((tid + ii * 256) & 15)];

    // prologue: h_eff[0]
#pragma unroll
    for (int ii = 0; ii < 4; ii++) {
        int e = tid + ii * 256;
        int b = e >> 4, j = e & 15;
        int f = f0 + j;
        bool dn = get_done(dones, b, dflag);
        float v = dn ? hiddens[(size_t)b * DD + f] : init_carry[(size_t)b * DD + f];
        g_heff[0][b * DD + f] = v;
    }
    __syncthreads();
    unsigned bar_no = 1;
    grid_barrier(RG * bar_no); bar_no++;

    int rh = tid >> 4;              // 0..15
    int ch = (tid & 15) << 2;       // 0..60

    for (int t = 0; t < TT; t++) {
        const float* hsrc = g_heff[t & 1];

        float acc[3][4];
#pragma unroll
        for (int nt = 0; nt < 3; nt++)
#pragma unroll
            for (int i = 0; i < 4; i++) acc[nt][i] = 0.0f;

        float4 pv0[4], pv1[4];
#define LOADC(dst, cidx) { \
    _Pragma("unroll") \
    for (int p = 0; p < 4; p++) \
        dst[p] = *(const float4*)&hsrc[(rh + p * 16) * DD + (cidx) * RKC + ch]; }
#define COMMIT(src, bufp) { \
    _Pragma("unroll") \
    for (int p = 0; p < 4; p++) { \
        float* d = &(bufp)[(rh + p * 16) * HS_S + ch]; \
        d[0] = f2tf_f(src[p].x); d[1] = f2tf_f(src[p].y); \
        d[2] = f2tf_f(src[p].z); d[3] = f2tf_f(src[p].w); } }

        LOADC(pv0, 0);
        LOADC(pv1, 1);

        // xproj tile availability (every other step advances the mblock)
        if ((t & 1) == 0) {
            if (tid == 0) {
                while (atomicAdd(&g_tilecnt[t >> 1], 0u) < (unsigned)NTILE_N) __nanosleep(64);
                __threadfence();
            }
            __syncthreads();
        }

        // epilogue operand prefetch (overlaps the GEMM below)
        float xr[4], xz[4], xn[4], he[4], hv[4];
        int dnp[4];
#pragma unroll
        for (int ii = 0; ii < 4; ii++) {
            int e = tid + ii * 256;
            int b = e >> 4, j = e & 15;
            int f = f0 + j;
            const float* xb = &g_xproj[((size_t)t * BB + b) * ND];
            xr[ii] = xb[f]; xz[ii] = xb[DD + f]; xn[ii] = xb[2 * DD + f];
            he[ii] = hsrc[b * DD + f];
            if (t < TT - 1) {
                dnp[ii] = get_done(dones, (t + 1) * BB + b, dflag) ? 1 : 0;
                hv[ii] = hiddens[((size_t)(t + 1) * BB + b) * DD + f];
            } else { dnp[ii] = 0; hv[ii] = 0.0f; }
        }

        COMMIT(pv0, hsA);
        LOADC(pv0, 2);
        __syncthreads();

        for (int kb = 0; kb < 16; kb++) {
            float* cbuf = (kb & 1) ? hsB : hsA;
            if (kb + 1 < 16) {
                if (kb & 1) { COMMIT(pv0, hsA); if (kb + 3 < 16) LOADC(pv0, kb + 3); }
                else        { COMMIT(pv1, hsB); if (kb + 3 < 16) LOADC(pv1, kb + 3); }
            }
            int kbase = kb * RKC;
#pragma unroll
            for (int kk = 0; kk < RKC; kk += 8) {
                unsigned a[4];
                int r0 = wm * 16;
                a[0] = fu(cbuf[(r0 + g) * HS_S + kk + tg]);
                a[1] = fu(cbuf[(r0 + 8 + g) * HS_S + kk + tg]);
                a[2] = fu(cbuf[(r0 + g) * HS_S + kk + 4 + tg]);
                a[3] = fu(cbuf[(r0 + 8 + g) * HS_S + kk + 4 + tg]);
#pragma unroll
                for (int nt = 0; nt < 3; nt++) {
                    int c0 = wn * 24 + nt * 8;
                    unsigned bfrag[2];
                    bfrag[0] = fu(ws[(c0 + g) * WT_S + kbase + kk + tg]);
                    bfrag[1] = fu(ws[(c0 + g) * WT_S + kbase + kk + 4 + tg]);
                    mma_tf32(acc[nt], a, bfrag);
                }
            }
            __syncthreads();
        }

        // GEMM result -> ps (hsA region; hsA last computed at kb=14, synced)
#pragma unroll
        for (int nt = 0; nt < 3; nt++) {
            int r0 = wm * 16 + g;
            int c0 = wn * 24 + nt * 8 + 2 * tg;
            ps[r0 * PS_S + c0]           = acc[nt][0];
            ps[r0 * PS_S + c0 + 1]       = acc[nt][1];
            ps[(r0 + 8) * PS_S + c0]     = acc[nt][2];
            ps[(r0 + 8) * PS_S + c0 + 1] = acc[nt][3];
        }
        __syncthreads();

        // gates + update (all operands prefetched)
#pragma unroll
        for (int ii = 0; ii < 4; ii++) {
            int e = tid + ii * 256;
            int b = e >> 4, j = e & 15;
            int f = f0 + j;
            float r = sigmoidf_(xr[ii] + ps[b * PS_S + j]);
            float z = sigmoidf_(xz[ii] + ps[b * PS_S + 16 + j]);
            float n = tanhf(xn[ii] + r * (ps[b * PS_S + 32 + j] + bh[ii]));
            float hnew = (1.0f - z) * n + z * he[ii];
            out[BB * DD + ((size_t)t * BB + b) * DD + f] = hnew;   // ys
            if (t == TT - 1) {
                out[(size_t)b * DD + f] = hnew;                     // final_carry
            } else {
                float nv = dnp[ii] ? hv[ii] : hnew;
                g_heff[(t & 1) ^ 1][b * DD + f] = nv;
            }
        }

        grid_barrier(RG * bar_no); bar_no++;
#undef LOADC
#undef COMMIT
    }
}

// ---------------- launch ----------------
extern "C" void kernel_launch(void* const* d_in, const int* in_sizes, int n_in,
                              void* d_out, int out_size) {
    const float* ins        = (const float*)d_in[0];
    const float* hiddens    = (const float*)d_in[1];
    const void*  dones      = (const void*)d_in[2];
    const float* init_carry = (const float*)d_in[3];
    const float* Wi         = (const float*)d_in[4];
    const float* Wh         = (const float*)d_in[5];
    const float* bi         = (const float*)d_in[6];
    const float* bhn        = (const float*)d_in[7];
    float* out = (float*)d_out;

    static int smem_set = 0;
    if (!smem_set) {
        cudaFuncSetAttribute(fused_kernel,
            cudaFuncAttributeMaxDynamicSharedMemorySize, GRU_SMEM_BYTES);
        smem_set = 1;
    }

    reset_kernel<<<1, 128>>>();
    fused_kernel<<<GRID_ALL, 256, GRU_SMEM_BYTES>>>(
        ins, hiddens, dones, init_carry, Wi, Wh, bi, bhn, out);
}